// round 8
// baseline (speedup 1.0000x reference)
#include <cuda_runtime.h>
#include <stdint.h>

// WeightedHashEmbedding, persistent-grid, 2 rows/warp interleaved + pipelined:
//   out[b, d] = (1/32) * sum_{c=0..31} table[idx0[b,c], d] * weights[idx1[b,c]]
//
// At the measured DRAM random-access ceiling (~5.93 TB/s, ~75% active).
// This round: interleave two output rows per warp so ~64 independent table
// LDGs are outstanding (near the M_max~55 per-warp cap), filling the
// FMA-drain tail at row boundaries. Streaming hints from R7 kept.

#define B_ROWS   32768
#define N_CHUNKS 32
#define DIM      64
#define NUM_SMS  148
#define BLOCKS_PER_SM 4

__device__ __forceinline__ void stcs_f2(float2* p, float2 v) {
    asm volatile("st.global.cs.v2.f32 [%0], {%1,%2};" :: "l"(p), "f"(v.x), "f"(v.y));
}

__global__ void __launch_bounds__(256, BLOCKS_PER_SM)
whe_kernel(const float* __restrict__ table,
           const float* __restrict__ weights,
           const int*   __restrict__ idx0,
           const int*   __restrict__ idx1,
           float2*      __restrict__ out)
{
    const int lane        = threadIdx.x & 31;
    const int warp_global = blockIdx.x * (blockDim.x >> 5) + (threadIdx.x >> 5);
    const int total_warps = gridDim.x * (blockDim.x >> 5);   // 4736
    const int stride      = total_warps * 2;                  // rows per sweep

    int b = warp_global * 2;                                   // rows b, b+1

    // Prologue: indices + pre-scaled weights for the first row pair.
    int   i0a = 0, i0b = 0;
    float wva = 0.0f, wvb = 0.0f;
    if (b < B_ROWS) {
        i0a = __ldcs(idx0 + (b    ) * N_CHUNKS + lane);
        i0b = __ldcs(idx0 + (b + 1) * N_CHUNKS + lane);
        const int i1a = __ldcs(idx1 + (b    ) * N_CHUNKS + lane);
        const int i1b = __ldcs(idx1 + (b + 1) * N_CHUNKS + lane);
        wva = __ldcs(weights + (uint32_t)i1a) * (1.0f / N_CHUNKS);
        wvb = __ldcs(weights + (uint32_t)i1b) * (1.0f / N_CHUNKS);
    }

    while (b < B_ROWS) {
        const int   ca = i0a,  cb = i0b;
        const float wa = wva,  wb = wvb;
        const int   bn = b + stride;

        // Prefetch next row pair's idx + weight gathers under this pair's
        // 64 table loads.
        if (bn < B_ROWS) {
            i0a = __ldcs(idx0 + (bn    ) * N_CHUNKS + lane);
            i0b = __ldcs(idx0 + (bn + 1) * N_CHUNKS + lane);
            const int i1a = __ldcs(idx1 + (bn    ) * N_CHUNKS + lane);
            const int i1b = __ldcs(idx1 + (bn + 1) * N_CHUNKS + lane);
            wva = __ldcs(weights + (uint32_t)i1a) * (1.0f / N_CHUNKS);
            wvb = __ldcs(weights + (uint32_t)i1b) * (1.0f / N_CHUNKS);
        }

        float2 accA = make_float2(0.0f, 0.0f);
        float2 accB = make_float2(0.0f, 0.0f);

        #pragma unroll
        for (int c = 0; c < N_CHUNKS; ++c) {
            const int   ta = __shfl_sync(0xffffffffu, ca, c);
            const int   tb = __shfl_sync(0xffffffffu, cb, c);
            const float fa = __shfl_sync(0xffffffffu, wa, c);
            const float fb = __shfl_sync(0xffffffffu, wb, c);
            const float2 va = __ldg(((const float2*)(table + (size_t)ta * DIM)) + lane);
            const float2 vb = __ldg(((const float2*)(table + (size_t)tb * DIM)) + lane);
            accA.x = fmaf(va.x, fa, accA.x);
            accA.y = fmaf(va.y, fa, accA.y);
            accB.x = fmaf(vb.x, fb, accB.x);
            accB.y = fmaf(vb.y, fb, accB.y);
        }

        stcs_f2(out + (b    ) * 32 + lane, accA);
        stcs_f2(out + (b + 1) * 32 + lane, accB);

        b = bn;
    }
}

extern "C" void kernel_launch(void* const* d_in, const int* in_sizes, int n_in,
                              void* d_out, int out_size)
{
    const float* table   = (const float*)d_in[0];
    const float* weights = (const float*)d_in[1];
    const int*   idx0    = (const int*)d_in[2];
    const int*   idx1    = (const int*)d_in[3];
    float2*      out     = (float2*)d_out;

    const int threads = 256;                       // 8 warps/block
    const int blocks  = NUM_SMS * BLOCKS_PER_SM;   // 592 — exactly resident
    whe_kernel<<<blocks, threads>>>(table, weights, idx0, idx1, out);
}

// round 9
// speedup vs baseline: 1.0373x; 1.0373x over previous
#include <cuda_runtime.h>
#include <stdint.h>

// WeightedHashEmbedding, persistent-grid, half-warp-per-row float4 layout:
//   out[b, d] = (1/32) * sum_{c=0..31} table[idx0[b,c], d] * weights[idx1[b,c]]
//
// Lanes 0-15 process row b, lanes 16-31 row b+1; each lane loads float4
// (16B), so ONE LDG.128 per chunk covers 512B across both rows. 32
// outstanding entries/warp (under the M_max~55 cap that R8 blew at 64)
// carrying 16KB in flight — 2x the bytes/warp of the 57.5us float2 kernel
// at the same LSU entry count.

#define B_ROWS   32768
#define N_CHUNKS 32
#define DIM      64
#define NUM_SMS  148
#define BLOCKS_PER_SM 4

__device__ __forceinline__ void stcs_f4(float4* p, float4 v) {
    asm volatile("st.global.cs.v4.f32 [%0], {%1,%2,%3,%4};"
                 :: "l"(p), "f"(v.x), "f"(v.y), "f"(v.z), "f"(v.w));
}

__global__ void __launch_bounds__(256, BLOCKS_PER_SM)
whe_kernel(const float* __restrict__ table,
           const float* __restrict__ weights,
           const int*   __restrict__ idx0,
           const int*   __restrict__ idx1,
           float4*      __restrict__ out)
{
    const int lane        = threadIdx.x & 31;
    const int half        = lane >> 4;          // 0: row A, 1: row B
    const int sub         = lane & 15;          // position within the row
    const int warp_global = blockIdx.x * (blockDim.x >> 5) + (threadIdx.x >> 5);
    const int total_warps = gridDim.x * (blockDim.x >> 5);   // 4736
    const int stride      = total_warps * 2;

    int b = warp_global * 2;                    // rows b (A), b+1 (B)

    // Prologue: lane c holds chunk c's indices / pre-scaled weight, per row.
    int   i0a = 0, i0b = 0;
    float wva = 0.0f, wvb = 0.0f;
    if (b < B_ROWS) {
        i0a = __ldcs(idx0 + (b    ) * N_CHUNKS + lane);
        i0b = __ldcs(idx0 + (b + 1) * N_CHUNKS + lane);
        const int i1a = __ldcs(idx1 + (b    ) * N_CHUNKS + lane);
        const int i1b = __ldcs(idx1 + (b + 1) * N_CHUNKS + lane);
        wva = __ldcs(weights + (uint32_t)i1a) * (1.0f / N_CHUNKS);
        wvb = __ldcs(weights + (uint32_t)i1b) * (1.0f / N_CHUNKS);
    }

    while (b < B_ROWS) {
        const int   ca = i0a,  cb = i0b;
        const float wa = wva,  wb = wvb;
        const int   bn = b + stride;

        // Prefetch next pair's idx + weight gathers under this pair's table loads.
        if (bn < B_ROWS) {
            i0a = __ldcs(idx0 + (bn    ) * N_CHUNKS + lane);
            i0b = __ldcs(idx0 + (bn + 1) * N_CHUNKS + lane);
            const int i1a = __ldcs(idx1 + (bn    ) * N_CHUNKS + lane);
            const int i1b = __ldcs(idx1 + (bn + 1) * N_CHUNKS + lane);
            wva = __ldcs(weights + (uint32_t)i1a) * (1.0f / N_CHUNKS);
            wvb = __ldcs(weights + (uint32_t)i1b) * (1.0f / N_CHUNKS);
        }

        float4 acc = make_float4(0.0f, 0.0f, 0.0f, 0.0f);

        #pragma unroll
        for (int c = 0; c < N_CHUNKS; ++c) {
            // Broadcast chunk c's row index / weight for both rows, then each
            // half-warp selects its own.
            const int   ta = __shfl_sync(0xffffffffu, ca, c);
            const int   tb = __shfl_sync(0xffffffffu, cb, c);
            const float fa = __shfl_sync(0xffffffffu, wa, c);
            const float fb = __shfl_sync(0xffffffffu, wb, c);
            const int   t  = half ? tb : ta;
            const float f  = half ? fb : fa;
            const float4 v = __ldg(((const float4*)(table + (size_t)t * DIM)) + sub);
            acc.x = fmaf(v.x, f, acc.x);
            acc.y = fmaf(v.y, f, acc.y);
            acc.z = fmaf(v.z, f, acc.z);
            acc.w = fmaf(v.w, f, acc.w);
        }

        // out row = 64 floats = 16 float4; half-warp h writes row b+h.
        stcs_f4(out + (size_t)(b + half) * 16 + sub, acc);

        b = bn;
    }
}

extern "C" void kernel_launch(void* const* d_in, const int* in_sizes, int n_in,
                              void* d_out, int out_size)
{
    const float* table   = (const float*)d_in[0];
    const float* weights = (const float*)d_in[1];
    const int*   idx0    = (const int*)d_in[2];
    const int*   idx1    = (const int*)d_in[3];
    float4*      out     = (float4*)d_out;

    const int threads = 256;                       // 8 warps/block
    const int blocks  = NUM_SMS * BLOCKS_PER_SM;   // 592 — exactly resident
    whe_kernel<<<blocks, threads>>>(table, weights, idx0, idx1, out);
}